// round 13
// baseline (speedup 1.0000x reference)
#include <cuda_runtime.h>

#define NV    8192
#define NCAM  20
#define CIN   2048
#define NH    4
#define NCOUT 2048
#define NJ    8192      /* NH*NCOUT */
#define NE    16384
#define NEG_SLOPE 0.2f
#define KB    32        /* k-split chunks for h_src */
#define KC    64        /* K per chunk (KB*KC = CIN) */
#define NBIN  4096

typedef unsigned long long ull;

// ---------------- scratch (device globals; no allocation) ----------------
__device__ float    g_part[KB * NCAM * NJ];   // 21MB k-split partials
__device__ float    g_hsrc[NCAM * NJ];        // [cam][h*COUT + c]
__device__ float    g_wd[NH * CIN];           // [h][k]
__device__ float    g_as[NCAM * NH];
__device__ float    g_ad[NV * NH];
__device__ int      g_cnt[NV * NCAM];         // per-vehicle camera edge counts
__device__ unsigned g_vmask[NV];
__device__ int      g_bin[NV];
__device__ int      g_hist[NBIN];
__device__ int      g_bofs[NBIN];
__device__ int      g_perm[NV];
__device__ int      g_is64;

// ---------------- helpers ----------------
__device__ __forceinline__ float warp_sum(float v) {
    #pragma unroll
    for (int o = 16; o; o >>= 1) v += __shfl_down_sync(0xffffffffu, v, o);
    return v;
}
__device__ __forceinline__ int eidx(const void* p, int i) {
    return g_is64 ? (int)((const long long*)p)[i] : ((const int*)p)[i];
}
#define FMA2(acc, w, c) \
    asm("fma.rn.f32x2 %0, %1, %2, %0;" : "+l"(acc) : "l"(w), "l"(c))

// ---------------- 1) zero accumulated scratch + int-width detect ----------------
__global__ void k_zero(const void* esrc) {
    int i = blockIdx.x * blockDim.x + threadIdx.x;
    if (i == 0) {
        const long long* p = (const long long*)esrc;
        int ok = 1;
        for (int q = 0; q < 64; q++) {
            long long v = p[q];
            if (v < 0 || v >= NCAM) { ok = 0; break; }
        }
        g_is64 = ok;
    }
    int s = gridDim.x * blockDim.x;
    for (int j = i; j < NV * NCAM; j += s) g_cnt[j] = 0;
    for (int j = i; j < NCAM * NH; j += s) g_as[j] = 0.f;
    for (int j = i; j < NBIN; j += s)      g_hist[j] = 0;
}

// ================= MEGA-1: hsrc (blocks 0..255) | wd (256..2303) | count (2304..2367)
#define M1_HSRC 256
#define M1_WD   (M1_HSRC + CIN)
#define M1_CNT  (M1_WD + NE / 256)

__global__ void __launch_bounds__(256, 2) k_mega1(const float* __restrict__ W,
                                                  const float* __restrict__ cam,
                                                  const float* __restrict__ att_dst,
                                                  const void* esrc, const void* edst) {
    int b = blockIdx.x, t = threadIdx.x;

    if (b < M1_HSRC) {
        int jb = b & 7, kb = b >> 3;
        int k0 = kb * KC;
        int j0 = jb * 1024 + t * 4;

        __shared__ ulonglong2 s_cam2[NCAM][KC / 2];   // 10KB
        for (int i = t; i < NCAM * KC; i += 256) {
            int n = i / KC, kc = i % KC;
            float c = cam[n * CIN + k0 + kc];
            float2 cc = make_float2(c, c);
            ((ull*)s_cam2)[n * KC + kc] = *(const ull*)&cc;
        }
        __syncthreads();

        ull acc[NCAM][2];
        #pragma unroll
        for (int n = 0; n < NCAM; n++) { acc[n][0] = 0ull; acc[n][1] = 0ull; }

        const float* Wp = W + (size_t)k0 * NJ + j0;
        #pragma unroll 2
        for (int kc2 = 0; kc2 < KC / 2; kc2++) {
            longlong2 w0 = *(const longlong2*)(Wp + (size_t)(2 * kc2) * NJ);
            longlong2 w1 = *(const longlong2*)(Wp + (size_t)(2 * kc2 + 1) * NJ);
            #pragma unroll
            for (int n = 0; n < NCAM; n++) {
                ulonglong2 cc = s_cam2[n][kc2];     // one LDS.128 feeds 2 kc
                FMA2(acc[n][0], (ull)w0.x, cc.x);
                FMA2(acc[n][1], (ull)w0.y, cc.x);
                FMA2(acc[n][0], (ull)w1.x, cc.y);
                FMA2(acc[n][1], (ull)w1.y, cc.y);
            }
        }

        float* pp = g_part + (size_t)kb * (NCAM * NJ) + j0;
        #pragma unroll
        for (int n = 0; n < NCAM; n++) {
            float2 lo = *(const float2*)&acc[n][0];
            float2 hi = *(const float2*)&acc[n][1];
            *(float4*)(pp + n * NJ) = make_float4(lo.x, lo.y, hi.x, hi.y);
        }
    } else if (b < M1_WD) {
        int k = b - M1_HSRC;
        const float4* row = (const float4*)(W + (size_t)k * NJ);
        const float4* ad4 = (const float4*)att_dst;
        float part[NH] = {0.f, 0.f, 0.f, 0.f};
        #pragma unroll
        for (int i = 0; i < 8; i++) {
            int j4 = i * 256 + t;
            float4 w = row[j4], a = ad4[j4];
            part[i >> 1] += w.x * a.x + w.y * a.y + w.z * a.z + w.w * a.w;
        }
        __shared__ float s[8][NH];
        int wid = t >> 5, lane = t & 31;
        #pragma unroll
        for (int h = 0; h < NH; h++) {
            float v = warp_sum(part[h]);
            if (lane == 0) s[wid][h] = v;
        }
        __syncthreads();
        if (t < NH) {
            float a = 0.f;
            #pragma unroll
            for (int w = 0; w < 8; w++) a += s[w][t];
            g_wd[t * CIN + k] = a;
        }
    } else {
        int e = (b - M1_WD) * 256 + t;
        if (e < NE) {
            int s = eidx(esrc, e), d = eidx(edst, e);
            atomicAdd(&g_cnt[d * NCAM + s], 1);
        }
    }
}

// ================= MEGA-2: a_d (0..1023) | hred (1024..1183) | mask+hist (1184..1215)
#define M2_AD 1024
#define M2_HR (M2_AD + (NCAM * NJ / 4) / 256)   /* 1184 */
#define M2_MH (M2_HR + NV / 256)                /* 1216 = total grid */

__global__ void __launch_bounds__(256) k_mega2(const float* __restrict__ x,
                                               const float* __restrict__ att_src) {
    int b = blockIdx.x, t = threadIdx.x;
    if (b < M2_AD) {
        // ---- a_d: warp per vehicle, 8 per block ----
        __shared__ __align__(16) float s_wd[NH * CIN];   // 32KB
        int wid = t >> 5, lane = t & 31;
        for (int i = t; i < NH * CIN; i += 256) s_wd[i] = g_wd[i];
        __syncthreads();
        int v = b * 8 + wid;
        const float4* xr = (const float4*)(x + (size_t)v * CIN);
        const float4* wd4 = (const float4*)s_wd;
        float part[NH] = {0.f, 0.f, 0.f, 0.f};
        #pragma unroll 4
        for (int i = 0; i < 16; i++) {
            int idx = lane + i * 32;
            float4 a = xr[idx];
            #pragma unroll
            for (int h = 0; h < NH; h++) {
                float4 wq = wd4[h * (CIN / 4) + idx];
                part[h] += a.x * wq.x + a.y * wq.y + a.z * wq.z + a.w * wq.w;
            }
        }
        #pragma unroll
        for (int h = 0; h < NH; h++) {
            float s0 = warp_sum(part[h]);
            if (lane == 0) g_ad[v * NH + h] = s0;
        }
    } else if (b < M2_HR) {
        // ---- reduce partials -> h_src (float4), fused a_s ----
        int gid = (b - M2_AD) * 256 + t;
        int lane = t & 31;
        int j4 = gid % (NJ / 4);
        int cm = gid / (NJ / 4);
        int j = j4 * 4, h = j / NCOUT;
        float4 s = make_float4(0.f, 0.f, 0.f, 0.f);
        const float4* P = (const float4*)g_part;
        #pragma unroll 8
        for (int kb = 0; kb < KB; kb++) {
            float4 v = P[(size_t)kb * (NCAM * NJ / 4) + gid];
            s.x += v.x; s.y += v.y; s.z += v.z; s.w += v.w;
        }
        ((float4*)g_hsrc)[gid] = s;
        float4 a = *(const float4*)(att_src + j);
        float p = warp_sum(s.x * a.x + s.y * a.y + s.z * a.z + s.w * a.w);
        if (lane == 0) atomicAdd(&g_as[cm * NH + h], p);
    } else {
        // ---- per-vehicle mask + hash histogram ----
        int v = (b - M2_HR) * 256 + t;        // FIX: was (b - M2_MH) -> negative OOB
        unsigned mask = 0;
        const int4* cp = (const int4*)&g_cnt[v * NCAM];
        #pragma unroll
        for (int q = 0; q < 5; q++) {
            int4 c4 = cp[q];
            if (c4.x) mask |= 1u << (q * 4 + 0);
            if (c4.y) mask |= 1u << (q * 4 + 1);
            if (c4.z) mask |= 1u << (q * 4 + 2);
            if (c4.w) mask |= 1u << (q * 4 + 3);
        }
        g_vmask[v] = mask;
        int bin = (int)((mask * 2654435761u) >> 20);   // 0..4095
        g_bin[v] = bin;
        atomicAdd(&g_hist[bin], 1);
    }
}

// ---------------- exclusive scan over 4096 bins (1 block, 1024 thr) ----------------
__global__ void __launch_bounds__(1024) k_scan() {
    __shared__ int s_w[32];
    int t = threadIdx.x, lane = t & 31, wid = t >> 5;
    int4 bv = ((const int4*)g_hist)[t];
    int s = bv.x + bv.y + bv.z + bv.w;
    int v = s;
    #pragma unroll
    for (int o = 1; o < 32; o <<= 1) {
        int n = __shfl_up_sync(0xffffffffu, v, o);
        if (lane >= o) v += n;
    }
    if (lane == 31) s_w[wid] = v;
    __syncthreads();
    if (wid == 0) {
        int w = s_w[lane];
        #pragma unroll
        for (int o = 1; o < 32; o <<= 1) {
            int n = __shfl_up_sync(0xffffffffu, w, o);
            if (lane >= o) w += n;
        }
        s_w[lane] = w;
    }
    __syncthreads();
    int excl = v - s + (wid ? s_w[wid - 1] : 0);
    int4 o4;
    o4.x = excl;
    o4.y = excl + bv.x;
    o4.z = excl + bv.x + bv.y;
    o4.w = excl + bv.x + bv.y + bv.z;
    ((int4*)g_bofs)[t] = o4;
}

// ---------------- scatter: build mask-grouped permutation ----------------
__global__ void k_scatter() {
    int v = blockIdx.x * 256 + threadIdx.x;
    if (v >= NV) return;
    int pos = atomicAdd(&g_bofs[g_bin[v]], 1);
    g_perm[pos] = v;
}

// ---------------- fused epilogue: 16 mask-grouped vehicles, reg accumulators ----
// union mode shares each cam's h_src load across all 16 vehicles.
__global__ void __launch_bounds__(128) k_final(const float* __restrict__ x,
                                               const float* __restrict__ bias,
                                               const float* __restrict__ alpha_p,
                                               float* __restrict__ out) {
    __shared__ float4   s_coef[16][NCAM];   // 5KB (zero-filled for inactive)
    __shared__ int      s_vid[16];
    __shared__ unsigned s_mask[16];
    __shared__ int      s_ulist[NCAM];
    __shared__ int      s_ucnt, s_deg;

    int t = threadIdx.x;
    int vbase = blockIdx.y * 16;          // grid.y = 512
    float a = alpha_p[0];
    float scale = a * 0.25f;

    for (int i = t; i < 16 * NCAM; i += 128)
        ((float4*)s_coef)[i] = make_float4(0.f, 0.f, 0.f, 0.f);
    __syncthreads();

    if (t < 16) {
        int v = g_perm[vbase + t];
        s_vid[t] = v;
        unsigned mask = g_vmask[v];
        s_mask[t] = mask;
        if (mask) {
            int cnt[NCAM];
            const int4* cp = (const int4*)&g_cnt[v * NCAM];
            #pragma unroll
            for (int q = 0; q < 5; q++) {
                int4 c4 = cp[q];
                cnt[q * 4 + 0] = c4.x; cnt[q * 4 + 1] = c4.y;
                cnt[q * 4 + 2] = c4.z; cnt[q * 4 + 3] = c4.w;
            }
            float4 adv = *(const float4*)&g_ad[v * NH];
            float ad[NH] = {adv.x, adv.y, adv.z, adv.w};
            float m[NH] = {-1e30f, -1e30f, -1e30f, -1e30f};
            unsigned mm = mask;
            while (mm) {
                int s = __ffs(mm) - 1; mm &= mm - 1;
                #pragma unroll
                for (int h = 0; h < NH; h++) {
                    float z = g_as[s * NH + h] + ad[h];
                    z = (z > 0.f) ? z : NEG_SLOPE * z;
                    m[h] = fmaxf(m[h], z);
                }
            }
            float den[NH] = {0.f, 0.f, 0.f, 0.f};
            mm = mask;
            while (mm) {
                int s = __ffs(mm) - 1; mm &= mm - 1;
                float p[NH];
                #pragma unroll
                for (int h = 0; h < NH; h++) {
                    float z = g_as[s * NH + h] + ad[h];
                    z = (z > 0.f) ? z : NEG_SLOPE * z;
                    p[h] = (float)cnt[s] * expf(z - m[h]);
                    den[h] += p[h];
                }
                s_coef[t][s] = make_float4(p[0], p[1], p[2], p[3]);
            }
            float4 r = make_float4(scale / den[0], scale / den[1],
                                   scale / den[2], scale / den[3]);
            mm = mask;
            while (mm) {
                int s = __ffs(mm) - 1; mm &= mm - 1;
                float4 pv = s_coef[t][s];
                pv.x *= r.x; pv.y *= r.y; pv.z *= r.z; pv.w *= r.w;
                s_coef[t][s] = pv;
            }
        }
    }
    __syncthreads();
    if (t == 0) {
        unsigned u = 0; int deg = 0;
        #pragma unroll
        for (int i = 0; i < 16; i++) { u |= s_mask[i]; deg += __popc(s_mask[i]); }
        int n = 0;
        while (u) { int c = __ffs(u) - 1; u &= u - 1; s_ulist[n++] = c; }
        s_ucnt = n; s_deg = deg;
    }
    __syncthreads();

    int c0 = blockIdx.x * 512 + t * 4;    // grid.x = 4
    float4 bb = *(const float4*)(bias + c0);
    float4 ab = make_float4(a * bb.x, a * bb.y, a * bb.z, a * bb.w);

    float4 acc[16];
    #pragma unroll
    for (int i = 0; i < 16; i++) {
        float4 xv = *(const float4*)(x + (size_t)s_vid[i] * CIN + c0);
        acc[i] = make_float4(xv.x + ab.x, xv.y + ab.y, xv.z + ab.z, xv.w + ab.w);
    }

    int un = s_ucnt, deg = s_deg;
    if (3 * un <= deg || un <= 4) {
        // ---- union mode: one h_src load per cam feeds all 16 vehicles ----
        for (int ci = 0; ci < un; ci++) {
            int camid = s_ulist[ci];
            const float* hp = &g_hsrc[camid * NJ + c0];
            float4 h0 = *(const float4*)(hp);
            float4 h1 = *(const float4*)(hp + NCOUT);
            float4 h2 = *(const float4*)(hp + 2 * NCOUT);
            float4 h3 = *(const float4*)(hp + 3 * NCOUT);
            #pragma unroll
            for (int i = 0; i < 16; i++) {
                float4 u = s_coef[i][camid];   // zero for inactive -> exact no-op
                acc[i].x += u.x * h0.x + u.y * h1.x + u.z * h2.x + u.w * h3.x;
                acc[i].y += u.x * h0.y + u.y * h1.y + u.z * h2.y + u.w * h3.y;
                acc[i].z += u.x * h0.z + u.y * h1.z + u.z * h2.z + u.w * h3.z;
                acc[i].w += u.x * h0.w + u.y * h1.w + u.z * h2.w + u.w * h3.w;
            }
        }
    } else {
        // ---- per-vehicle mode (R8 style) ----
        #pragma unroll
        for (int i = 0; i < 16; i++) {
            unsigned m = s_mask[i];
            while (m) {
                int camid = __ffs(m) - 1;
                m &= m - 1;
                float4 u = s_coef[i][camid];
                const float* hp = &g_hsrc[camid * NJ + c0];
                float4 h0 = *(const float4*)(hp);
                float4 h1 = *(const float4*)(hp + NCOUT);
                float4 h2 = *(const float4*)(hp + 2 * NCOUT);
                float4 h3 = *(const float4*)(hp + 3 * NCOUT);
                acc[i].x += u.x * h0.x + u.y * h1.x + u.z * h2.x + u.w * h3.x;
                acc[i].y += u.x * h0.y + u.y * h1.y + u.z * h2.y + u.w * h3.y;
                acc[i].z += u.x * h0.z + u.y * h1.z + u.z * h2.z + u.w * h3.z;
                acc[i].w += u.x * h0.w + u.y * h1.w + u.z * h2.w + u.w * h3.w;
            }
        }
    }

    #pragma unroll
    for (int i = 0; i < 16; i++)
        __stcs((float4*)(out + (size_t)s_vid[i] * CIN + c0), acc[i]);
}

// ---------------- launch ----------------
extern "C" void kernel_launch(void* const* d_in, const int* in_sizes, int n_in,
                              void* d_out, int out_size) {
    const float* x_vehicle = (const float*)d_in[0];
    const float* cam_table = (const float*)d_in[1];
    const float* W         = (const float*)d_in[2];
    const float* att_src   = (const float*)d_in[3];
    const float* att_dst   = (const float*)d_in[4];
    const float* bias      = (const float*)d_in[5];
    const float* alpha     = (const float*)d_in[6];
    // d_in[7] = unique_cams == arange(NCAM); identity gather skipped
    const void*  esrc      = d_in[8];
    const void*  edst      = d_in[9];
    float* out = (float*)d_out;

    k_zero<<<128, 256>>>(esrc);                                     // 1
    k_mega1<<<M1_CNT, 256>>>(W, cam_table, att_dst, esrc, edst);    // 2
    k_mega2<<<M2_MH, 256>>>(x_vehicle, att_src);                    // 3  FIX: grid was M2_MH + NV/256
    k_scan<<<1, 1024>>>();                                          // 4
    k_scatter<<<NV / 256, 256>>>();                                 // 5
    {
        dim3 g(4, NV / 16);
        k_final<<<g, 128>>>(x_vehicle, bias, alpha, out);           // 6
    }
}

// round 14
// speedup vs baseline: 1.1244x; 1.1244x over previous
#include <cuda_runtime.h>

#define NV    8192
#define NCAM  20
#define CIN   2048
#define NH    4
#define NCOUT 2048
#define NJ    8192      /* NH*NCOUT */
#define NE    16384
#define NEG_SLOPE 0.2f
#define KB    32        /* k-split chunks for h_src */
#define KC    64        /* K per chunk (KB*KC = CIN) */

typedef unsigned long long ull;

// ---------------- scratch (device globals; no allocation) ----------------
__device__ float    g_part[KB * NCAM * NJ];   // 21MB k-split partials
__device__ float    g_hsrc[NCAM * NJ];        // [cam][h*COUT + c]
__device__ float    g_wd[NH * CIN];           // [h][k]
__device__ float    g_as[NCAM * NH];
__device__ float    g_ad[NV * NH];
__device__ int      g_cnt[NV * NCAM];         // per-vehicle camera edge counts
__device__ int      g_is64;

// ---------------- helpers ----------------
__device__ __forceinline__ float warp_sum(float v) {
    #pragma unroll
    for (int o = 16; o; o >>= 1) v += __shfl_down_sync(0xffffffffu, v, o);
    return v;
}
__device__ __forceinline__ int eidx(const void* p, int i) {
    return g_is64 ? (int)((const long long*)p)[i] : ((const int*)p)[i];
}
#define FMA2(acc, w, c) \
    asm("fma.rn.f32x2 %0, %1, %2, %0;" : "+l"(acc) : "l"(w), "l"(c))

// ---------------- 1) zero accumulated scratch + int-width detect ----------------
__global__ void k_zero(const void* esrc) {
    int i = blockIdx.x * blockDim.x + threadIdx.x;
    if (i == 0) {
        const long long* p = (const long long*)esrc;
        int ok = 1;
        for (int q = 0; q < 64; q++) {
            long long v = p[q];
            if (v < 0 || v >= NCAM) { ok = 0; break; }
        }
        g_is64 = ok;
    }
    int s = gridDim.x * blockDim.x;
    for (int j = i; j < NV * NCAM; j += s) g_cnt[j] = 0;
    for (int j = i; j < NCAM * NH; j += s) g_as[j] = 0.f;
}

// ================= MEGA-1: hsrc (blocks 0..255) | wd (256..2303) | count (2304..2367)
#define M1_HSRC 256
#define M1_WD   (M1_HSRC + CIN)
#define M1_CNT  (M1_WD + NE / 256)

__global__ void __launch_bounds__(256, 2) k_mega1(const float* __restrict__ W,
                                                  const float* __restrict__ cam,
                                                  const float* __restrict__ att_dst,
                                                  const void* esrc, const void* edst) {
    int b = blockIdx.x, t = threadIdx.x;

    if (b < M1_HSRC) {
        // ---- h_src partials: 8 j-blocks of 1024 cols x 32 k-chunks of 64 ----
        int jb = b & 7, kb = b >> 3;
        int k0 = kb * KC;
        int j0 = jb * 1024 + t * 4;

        __shared__ ulonglong2 s_cam2[NCAM][KC / 2];   // 10KB
        for (int i = t; i < NCAM * KC; i += 256) {
            int n = i / KC, kc = i % KC;
            float c = cam[n * CIN + k0 + kc];
            float2 cc = make_float2(c, c);
            ((ull*)s_cam2)[n * KC + kc] = *(const ull*)&cc;
        }
        __syncthreads();

        ull acc[NCAM][2];
        #pragma unroll
        for (int n = 0; n < NCAM; n++) { acc[n][0] = 0ull; acc[n][1] = 0ull; }

        const float* Wp = W + (size_t)k0 * NJ + j0;
        #pragma unroll 2
        for (int kc2 = 0; kc2 < KC / 2; kc2++) {
            longlong2 w0 = *(const longlong2*)(Wp + (size_t)(2 * kc2) * NJ);
            longlong2 w1 = *(const longlong2*)(Wp + (size_t)(2 * kc2 + 1) * NJ);
            #pragma unroll
            for (int n = 0; n < NCAM; n++) {
                ulonglong2 cc = s_cam2[n][kc2];     // one LDS.128 feeds 2 kc
                FMA2(acc[n][0], (ull)w0.x, cc.x);
                FMA2(acc[n][1], (ull)w0.y, cc.x);
                FMA2(acc[n][0], (ull)w1.x, cc.y);
                FMA2(acc[n][1], (ull)w1.y, cc.y);
            }
        }

        float* pp = g_part + (size_t)kb * (NCAM * NJ) + j0;
        #pragma unroll
        for (int n = 0; n < NCAM; n++) {
            float2 lo = *(const float2*)&acc[n][0];
            float2 hi = *(const float2*)&acc[n][1];
            *(float4*)(pp + n * NJ) = make_float4(lo.x, lo.y, hi.x, hi.y);
        }
    } else if (b < M1_WD) {
        // ---- wd[h][k] = sum_j W[k,j]*att_dst[j] (64MB stream, overlaps hsrc) ----
        int k = b - M1_HSRC;
        const float4* row = (const float4*)(W + (size_t)k * NJ);
        const float4* ad4 = (const float4*)att_dst;
        float part[NH] = {0.f, 0.f, 0.f, 0.f};
        #pragma unroll
        for (int i = 0; i < 8; i++) {
            int j4 = i * 256 + t;
            float4 w = row[j4], a = ad4[j4];
            part[i >> 1] += w.x * a.x + w.y * a.y + w.z * a.z + w.w * a.w;
        }
        __shared__ float s[8][NH];
        int wid = t >> 5, lane = t & 31;
        #pragma unroll
        for (int h = 0; h < NH; h++) {
            float v = warp_sum(part[h]);
            if (lane == 0) s[wid][h] = v;
        }
        __syncthreads();
        if (t < NH) {
            float a = 0.f;
            #pragma unroll
            for (int w = 0; w < 8; w++) a += s[w][t];
            g_wd[t * CIN + k] = a;
        }
    } else {
        // ---- edge counts ----
        int e = (b - M1_WD) * 256 + t;
        if (e < NE) {
            int s = eidx(esrc, e), d = eidx(edst, e);
            atomicAdd(&g_cnt[d * NCAM + s], 1);
        }
    }
}

// ================= MEGA-2: a_d (blocks 0..1023) | hred (1024..1183)
#define M2_AD 1024

__global__ void __launch_bounds__(256) k_mega2(const float* __restrict__ x,
                                               const float* __restrict__ att_src) {
    int b = blockIdx.x, t = threadIdx.x;
    if (b < M2_AD) {
        // ---- a_d: warp per vehicle, 8 per block ----
        __shared__ __align__(16) float s_wd[NH * CIN];   // 32KB
        int wid = t >> 5, lane = t & 31;
        for (int i = t; i < NH * CIN; i += 256) s_wd[i] = g_wd[i];
        __syncthreads();
        int v = b * 8 + wid;
        const float4* xr = (const float4*)(x + (size_t)v * CIN);
        const float4* wd4 = (const float4*)s_wd;
        float part[NH] = {0.f, 0.f, 0.f, 0.f};
        #pragma unroll 4
        for (int i = 0; i < 16; i++) {
            int idx = lane + i * 32;
            float4 a = xr[idx];
            #pragma unroll
            for (int h = 0; h < NH; h++) {
                float4 wq = wd4[h * (CIN / 4) + idx];
                part[h] += a.x * wq.x + a.y * wq.y + a.z * wq.z + a.w * wq.w;
            }
        }
        #pragma unroll
        for (int h = 0; h < NH; h++) {
            float s0 = warp_sum(part[h]);
            if (lane == 0) g_ad[v * NH + h] = s0;
        }
    } else {
        // ---- reduce partials -> h_src (float4), fused a_s ----
        int gid = (b - M2_AD) * 256 + t;      // over NCAM*NJ/4 = 40960
        int lane = t & 31;
        int j4 = gid % (NJ / 4);
        int cm = gid / (NJ / 4);
        int j = j4 * 4, h = j / NCOUT;
        float4 s = make_float4(0.f, 0.f, 0.f, 0.f);
        const float4* P = (const float4*)g_part;
        #pragma unroll 8
        for (int kb = 0; kb < KB; kb++) {
            float4 v = P[(size_t)kb * (NCAM * NJ / 4) + gid];
            s.x += v.x; s.y += v.y; s.z += v.z; s.w += v.w;
        }
        ((float4*)g_hsrc)[gid] = s;
        float4 a = *(const float4*)(att_src + j);
        float p = warp_sum(s.x * a.x + s.y * a.y + s.z * a.z + s.w * a.w);
        if (lane == 0) atomicAdd(&g_as[cm * NH + h], p);
    }
}

// ---------------- fused epilogue with in-block softmax ----------------
// 16 vehicles/block (grid 4x512 = 2048 blocks -> ~11 resident blocks/SM) for
// latency hiding; 512-col tiles keep per-cam h_src slices L1-resident.
__global__ void __launch_bounds__(128) k_final(const float* __restrict__ x,
                                               const float* __restrict__ bias,
                                               const float* __restrict__ alpha_p,
                                               float* __restrict__ out) {
    __shared__ float4   s_coef[16][NCAM];   // 5KB, pre-scaled coefficients
    __shared__ unsigned s_mask[16];

    int t = threadIdx.x;
    int vbase = blockIdx.y * 16;          // grid.y = 512
    float a = alpha_p[0];
    float scale = a * 0.25f;

    // ---- prologue: per-vehicle softmax (threads 0..15) ----
    if (t < 16) {
        int v = vbase + t;
        unsigned mask = 0;
        int cnt[NCAM];
        const int4* cp = (const int4*)&g_cnt[v * NCAM];
        #pragma unroll
        for (int q = 0; q < 5; q++) {
            int4 c4 = cp[q];
            cnt[q * 4 + 0] = c4.x; cnt[q * 4 + 1] = c4.y;
            cnt[q * 4 + 2] = c4.z; cnt[q * 4 + 3] = c4.w;
        }
        #pragma unroll
        for (int s = 0; s < NCAM; s++) if (cnt[s]) mask |= 1u << s;
        s_mask[t] = mask;
        if (mask) {
            float4 adv = *(const float4*)&g_ad[v * NH];
            float ad[NH] = {adv.x, adv.y, adv.z, adv.w};
            float m[NH] = {-1e30f, -1e30f, -1e30f, -1e30f};
            unsigned mm = mask;
            while (mm) {
                int s = __ffs(mm) - 1; mm &= mm - 1;
                #pragma unroll
                for (int h = 0; h < NH; h++) {
                    float z = g_as[s * NH + h] + ad[h];
                    z = (z > 0.f) ? z : NEG_SLOPE * z;
                    m[h] = fmaxf(m[h], z);
                }
            }
            float den[NH] = {0.f, 0.f, 0.f, 0.f};
            mm = mask;
            while (mm) {
                int s = __ffs(mm) - 1; mm &= mm - 1;
                float p[NH];
                #pragma unroll
                for (int h = 0; h < NH; h++) {
                    float z = g_as[s * NH + h] + ad[h];
                    z = (z > 0.f) ? z : NEG_SLOPE * z;
                    p[h] = (float)cnt[s] * expf(z - m[h]);
                    den[h] += p[h];
                }
                s_coef[t][s] = make_float4(p[0], p[1], p[2], p[3]);
            }
            float4 r = make_float4(scale / den[0], scale / den[1],
                                   scale / den[2], scale / den[3]);
            mm = mask;
            while (mm) {
                int s = __ffs(mm) - 1; mm &= mm - 1;
                float4 pv = s_coef[t][s];
                pv.x *= r.x; pv.y *= r.y; pv.z *= r.z; pv.w *= r.w;
                s_coef[t][s] = pv;
            }
        }
    }
    __syncthreads();

    // ---- main loop ----
    int c0 = blockIdx.x * 512 + t * 4;    // grid.x = 4
    float4 bb = *(const float4*)(bias + c0);
    float4 ab = make_float4(a * bb.x, a * bb.y, a * bb.z, a * bb.w);
    for (int vi = 0; vi < 16; vi += 4) {
        int v = vbase + vi;
        float4 xv[4];
        #pragma unroll
        for (int p = 0; p < 4; p++)
            xv[p] = *(const float4*)(x + (size_t)(v + p) * CIN + c0);
        #pragma unroll
        for (int p = 0; p < 4; p++) {
            float4 o = make_float4(xv[p].x + ab.x, xv[p].y + ab.y,
                                   xv[p].z + ab.z, xv[p].w + ab.w);
            unsigned m = s_mask[vi + p];
            while (m) {
                int camid = __ffs(m) - 1;
                m &= m - 1;
                float4 u = s_coef[vi + p][camid];   // pre-scaled
                const float* hp = &g_hsrc[camid * NJ + c0];
                float4 h0 = *(const float4*)(hp);
                float4 h1 = *(const float4*)(hp + NCOUT);
                float4 h2 = *(const float4*)(hp + 2 * NCOUT);
                float4 h3 = *(const float4*)(hp + 3 * NCOUT);
                o.x += u.x * h0.x + u.y * h1.x + u.z * h2.x + u.w * h3.x;
                o.y += u.x * h0.y + u.y * h1.y + u.z * h2.y + u.w * h3.y;
                o.z += u.x * h0.z + u.y * h1.z + u.z * h2.z + u.w * h3.z;
                o.w += u.x * h0.w + u.y * h1.w + u.z * h2.w + u.w * h3.w;
            }
            __stcs((float4*)(out + (size_t)(v + p) * CIN + c0), o);
        }
    }
}

// ---------------- launch ----------------
extern "C" void kernel_launch(void* const* d_in, const int* in_sizes, int n_in,
                              void* d_out, int out_size) {
    const float* x_vehicle = (const float*)d_in[0];
    const float* cam_table = (const float*)d_in[1];
    const float* W         = (const float*)d_in[2];
    const float* att_src   = (const float*)d_in[3];
    const float* att_dst   = (const float*)d_in[4];
    const float* bias      = (const float*)d_in[5];
    const float* alpha     = (const float*)d_in[6];
    // d_in[7] = unique_cams == arange(NCAM); identity gather skipped
    const void*  esrc      = d_in[8];
    const void*  edst      = d_in[9];
    float* out = (float*)d_out;

    k_zero<<<128, 256>>>(esrc);                                     // 1
    k_mega1<<<M1_CNT, 256>>>(W, cam_table, att_dst, esrc, edst);    // 2
    k_mega2<<<M2_AD + (NCAM * NJ / 4) / 256, 256>>>(x_vehicle, att_src); // 3
    {
        dim3 g(4, NV / 16);
        k_final<<<g, 128>>>(x_vehicle, bias, alpha, out);           // 4
    }
}